// round 15
// baseline (speedup 1.0000x reference)
#include <cuda_runtime.h>
#include <cuda_bf16.h>
#include <cuda_fp16.h>
#include <cstdint>
#include <cstddef>

// Problem constants (dataset is fixed)
#define BATCH   32
#define TOK     256
#define DIM     1024
#define NPER    64
#define NNODES  2048          // BATCH*NPER
#define NEDGE   65536
#define OUTSZ   6176          // 32 energy + 2048*3 forces

// ---------------------------------------------------------------------------
// Scratch (static __device__ — no allocation allowed)
// ---------------------------------------------------------------------------
__device__ __half g_Ph[NNODES * 2 * DIM];     // P fp16: [n][0:1024]=P1+bf1, [n][1024:2048]=P2
__device__ __half g_Ah[NNODES * DIM];         // nodes fp16
__device__ __half g_Bh[2 * DIM * DIM];        // Wf1^T fp16

__device__ __forceinline__ float gelu_exact(float v) {
    return 0.5f * v * (1.0f + erff(v * 0.70710678118654752440f));
}

// half2 tanh-gelu, returns 2*gelu(h): h*th + h  (0.5 folded into Wf2 weights)
__device__ __forceinline__ __half2 gelu2x_h2(__half2 h) {
    const __half2 c1 = __float2half2_rn(0.7978845608028654f);
    const __half2 c2 = __float2half2_rn(0.0356774080957f);
    __half2 t = __hmul2(h, h);
    __half2 p = __hfma2(t, c2, c1);
    __half2 u = __hmul2(h, p);
    uint32_t uu = *(uint32_t*)&u, th;
    asm("tanh.approx.f16x2 %0, %1;" : "=r"(th) : "r"(uu));
    __half2 th2 = *(__half2*)&th;
    return __hfma2(h, th2, h);
}

__device__ __forceinline__ uint32_t smem_u32(const void* p) {
    uint32_t a;
    asm("{ .reg .u64 t; cvta.to.shared.u64 t, %1; cvt.u32.u64 %0, t; }" : "=r"(a) : "l"(p));
    return a;
}

#define CP_ASYNC16(dst, src) asm volatile("cp.async.cg.shared.global [%0], [%1], 16;" :: "r"(dst), "l"(src))
#define CP_COMMIT()          asm volatile("cp.async.commit_group;" ::: "memory")

__device__ __forceinline__ void ldm_x4(uint32_t* r, uint32_t addr) {
    asm volatile("ldmatrix.sync.aligned.m8n8.x4.shared.b16 {%0,%1,%2,%3}, [%4];"
        : "=r"(r[0]), "=r"(r[1]), "=r"(r[2]), "=r"(r[3]) : "r"(addr));
}

__device__ __forceinline__ void mma16816h(float* d, const uint32_t* a, const uint32_t* b) {
    asm volatile("mma.sync.aligned.m16n8k16.row.col.f32.f16.f16.f32 "
        "{%0,%1,%2,%3}, {%4,%5,%6,%7}, {%8,%9}, {%0,%1,%2,%3};"
        : "+f"(d[0]), "+f"(d[1]), "+f"(d[2]), "+f"(d[3])
        : "r"(a[0]), "r"(a[1]), "r"(a[2]), "r"(a[3]), "r"(b[0]), "r"(b[1]));
}

// ---------------------------------------------------------------------------
// Convert nodes -> fp16; also initializes the output
// ---------------------------------------------------------------------------
__global__ void __launch_bounds__(256) k_cvt_a(const float* __restrict__ x,
                                               float* __restrict__ out,
                                               const float* __restrict__ be2) {
    int id = blockIdx.x * 256 + threadIdx.x;
    if (id < OUTSZ) out[id] = (id < BATCH) ? be2[0] : 0.0f;
    int base = id * 4;
    int n = base >> 10;
    int k = base & (DIM - 1);
    int nr = ((n >> 6) << 8) + 1 + (n & 63);
    float4 v = *(const float4*)(x + (size_t)nr * DIM + k);
    __half2* dh = (__half2*)(g_Ah + (size_t)n * DIM + k);
    dh[0] = __floats2half2_rn(v.x, v.y);
    dh[1] = __floats2half2_rn(v.z, v.w);
}

// ---------------------------------------------------------------------------
// Transpose Wf1 -> K-major fp16. Coalesced 4B stores.
// grid (64 jt, 16 kt), block (32, 32)
// ---------------------------------------------------------------------------
__global__ void k_cvt_w(const float* __restrict__ Wf1) {
    __shared__ float s[64][33];
    int jp0 = blockIdx.x * 32;
    int k0  = blockIdx.y * 64;
    int half = jp0 >> 10;
    int jb = jp0 & (DIM - 1);
    int tx = threadIdx.x, ty = threadIdx.y;
#pragma unroll
    for (int r = 0; r < 2; r++) {
        int kk = k0 + ty + r * 32;
        s[ty + r * 32][tx] = Wf1[(size_t)(half * DIM + kk) * DIM + jb + tx];
    }
    __syncthreads();
    int jp = jp0 + ty;
    *(__half2*)(g_Bh + (size_t)jp * DIM + k0 + 2 * tx) =
        __floats2half2_rn(s[2 * tx][ty], s[2 * tx + 1][ty]);
}

// ---------------------------------------------------------------------------
// mma.sync fp16 GEMM: D = Ah*Bh (fp32 accum)
// BM=BN=128, BK=64, 2-stage cp.async pipeline.
// ---------------------------------------------------------------------------
#define BK       64
#define TSTRIDE  72                          // halves per smem row (144B pitch)
#define TILE_B   (128 * TSTRIDE * 2)         // 18432 B per tile
#define STAGE_B  (2 * TILE_B)                // Ah, Bh = 36864 B
#define NSTAGE   2
#define GEMM_SMEM (NSTAGE * STAGE_B + 16)
#define NKT      (DIM / BK)                  // 16

__global__ void __launch_bounds__(256, 2) k_gemm_mma(const float* __restrict__ bf1) {
    extern __shared__ __align__(16) char smem_raw[];
    const uint32_t sb = smem_u32(smem_raw);
    const int tid  = threadIdx.x;
    const int lane = tid & 31;
    const int warp = tid >> 5;
    const int n0 = blockIdx.x * 128;
    const int m0 = blockIdx.y * 128;
    const int wm0 = (warp >> 2) * 64;
    const int wn0 = (warp & 3) * 32;

    float acc[4][4][4];
#pragma unroll
    for (int i = 0; i < 4; i++)
#pragma unroll
        for (int j = 0; j < 4; j++)
#pragma unroll
            for (int q = 0; q < 4; q++) acc[i][j][q] = 0.0f;

#define PREFETCH(stage, kb) do {                                                    \
    uint32_t st = sb + (stage) * STAGE_B;                                           \
    _Pragma("unroll")                                                               \
    for (int gi = 0; gi < 4; gi++) {                                                \
        int g = tid + 256 * gi;                                                     \
        int r = g >> 3;                                                             \
        int c = g & 7;                                                              \
        uint32_t off = r * 144 + c * 16;                                            \
        size_t eA = (size_t)(m0 + r) * DIM + (kb) + c * 8;                          \
        size_t eB = (size_t)(n0 + r) * DIM + (kb) + c * 8;                          \
        CP_ASYNC16(st + off,          g_Ah + eA);                                   \
        CP_ASYNC16(st + TILE_B + off, g_Bh + eB);                                   \
    }                                                                               \
} while (0)

    PREFETCH(0, 0);
    CP_COMMIT();

    int stage = 0;
    for (int kt = 0; kt < NKT; kt++) {
        if (kt + 1 < NKT) {
            PREFETCH(stage ^ 1, (kt + 1) * BK);
            CP_COMMIT();
            asm volatile("cp.async.wait_group 1;" ::: "memory");
        } else {
            asm volatile("cp.async.wait_group 0;" ::: "memory");
        }
        __syncthreads();

        uint32_t st  = sb + stage * STAGE_B;
        uint32_t sAh = st;
        uint32_t sBh = st + TILE_B;

#pragma unroll
        for (int ks = 0; ks < 4; ks++) {
            uint32_t k0b = ks * 32;
            uint32_t ah[4][4], bh[2][4];
#pragma unroll
            for (int mi = 0; mi < 4; mi++) {
                uint32_t row = wm0 + mi * 16 + (lane & 15);
                uint32_t off = row * 144 + k0b + ((lane >> 4) << 4);
                ldm_x4(ah[mi], sAh + off);
            }
#pragma unroll
            for (int nj = 0; nj < 2; nj++) {
                uint32_t row = wn0 + nj * 16 + (lane & 7) + ((lane >> 4) << 3);
                uint32_t off = row * 144 + k0b + (((lane >> 3) & 1) << 4);
                ldm_x4(bh[nj], sBh + off);
            }
#pragma unroll
            for (int mi = 0; mi < 4; mi++)
#pragma unroll
                for (int nt = 0; nt < 4; nt++)
                    mma16816h(acc[mi][nt], ah[mi], &bh[nt >> 1][(nt & 1) * 2]);
        }
        __syncthreads();
        stage ^= 1;
    }

#pragma unroll
    for (int mi = 0; mi < 4; mi++) {
        int gm = m0 + wm0 + mi * 16 + (lane >> 2);
#pragma unroll
        for (int nt = 0; nt < 4; nt++) {
            int gn = n0 + wn0 + nt * 8 + ((lane & 3) << 1);
            float b0 = 0.0f, b1 = 0.0f;
            if (gn < DIM) { b0 = bf1[gn]; b1 = bf1[gn + 1]; }
            __half2 v0 = __floats2half2_rn(acc[mi][nt][0] + b0, acc[mi][nt][1] + b1);
            __half2 v1 = __floats2half2_rn(acc[mi][nt][2] + b0, acc[mi][nt][3] + b1);
            *(__half2*)(g_Ph + (size_t)gm * (2 * DIM) + gn)       = v0;
            *(__half2*)(g_Ph + (size_t)(gm + 8) * (2 * DIM) + gn) = v1;
        }
    }
}

// ---------------------------------------------------------------------------
// Edge phase: 8 edges per warp. All edge metadata (indices, dist, dvec)
// prefetched lane-parallel at warp start and broadcast via shfl — the only
// per-edge memory chain left is the P gather. Force atomics distributed
// across lanes 3ee..3ee+2.
// ---------------------------------------------------------------------------
#define EPW 8
__global__ void __launch_bounds__(256) k_edge(
    const int* __restrict__ ei, const float* __restrict__ dvec,
    const float* __restrict__ dist, const float* __restrict__ Wf2,
    const float* __restrict__ bf2, float* __restrict__ out) {
    __shared__ __half2 s_wh[512];             // Wf2 * 0.5 as half2 (2 KB)
    int tid = threadIdx.x;
    {
        float4 w = ((const float4*)Wf2)[tid];
        s_wh[2 * tid]     = __floats2half2_rn(w.x * 0.5f, w.y * 0.5f);
        s_wh[2 * tid + 1] = __floats2half2_rn(w.z * 0.5f, w.w * 0.5f);
    }
    __syncthreads();

    int warp = tid >> 5;
    int lane = tid & 31;
    int e0 = (blockIdx.x * 8 + warp) * EPW;
    float bf2v = bf2[0];

    // lane-parallel metadata prefetch (one batch of LDGs per warp)
    int   pi = (lane < EPW) ? ei[e0 + lane] : 0;
    int   pj = (lane < EPW) ? ei[NEDGE + e0 + lane] : 0;
    float pr = (lane < EPW) ? __frcp_rn(dist[e0 + lane]) : 0.0f;
    float pv = (lane < 3 * EPW) ? dvec[3 * e0 + lane] : 0.0f;

#pragma unroll
    for (int ee = 0; ee < EPW; ee++) {
        int i = __shfl_sync(0xffffffffu, pi, ee);
        int j = __shfl_sync(0xffffffffu, pj, ee);
        const uint4* r1 = (const uint4*)(g_Ph + (size_t)i * (2 * DIM));
        const uint4* r2 = (const uint4*)(g_Ph + (size_t)j * (2 * DIM) + DIM);

        float acc = 0.0f;
#pragma unroll
        for (int q = 0; q < 4; q++) {
            uint4 a4 = r1[lane + 32 * q];
            uint4 c4 = r2[lane + 32 * q];
            uint4 wv = ((const uint4*)s_wh)[lane + 32 * q];   // 4 half2 weights
            const __half2* ah = (const __half2*)&a4;
            const __half2* ch = (const __half2*)&c4;
            const __half2* wh = (const __half2*)&wv;
            __half2 hacc = __hmul2(gelu2x_h2(__hadd2(ah[0], ch[0])), wh[0]);
            hacc = __hfma2(gelu2x_h2(__hadd2(ah[1], ch[1])), wh[1], hacc);
            hacc = __hfma2(gelu2x_h2(__hadd2(ah[2], ch[2])), wh[2], hacc);
            hacc = __hfma2(gelu2x_h2(__hadd2(ah[3], ch[3])), wh[3], hacc);
            float2 f = __half22float2(hacc);
            acc += f.x + f.y;
        }
#pragma unroll
        for (int o = 16; o; o >>= 1) acc += __shfl_xor_sync(0xffffffffu, acc, o);
        // acc now in all lanes
        float rinv = __shfl_sync(0xffffffffu, pr, ee);
        float s = (acc + bf2v) * rinv;
        int lr = lane - 3 * ee;                // 0..2 for the 3 assigned lanes
        if (lr >= 0 && lr < 3) {
            atomicAdd(out + BATCH + (size_t)i * 3 + lr, s * pv);
        }
    }
}

// ---------------------------------------------------------------------------
// Energy head with in-block LayerNorm, 4 batch rows per block.
// grid (32 jt, 8 bg), 128 threads.
// ---------------------------------------------------------------------------
__global__ void __launch_bounds__(128) k_energy(
    const float* __restrict__ x, const float* __restrict__ ln_g,
    const float* __restrict__ ln_b,
    const float* __restrict__ We1, const float* __restrict__ be1,
    const float* __restrict__ We2, float* __restrict__ out) {
    int bg = blockIdx.y;
    int j0 = blockIdx.x * 32;
    int tid = threadIdx.x;
    int lane = tid & 31, wid = tid >> 5;

    __shared__ float sh[4][DIM];
    __shared__ float wred[4][4][2];
    __shared__ float stats[4][2];
    __shared__ float red[4][128];

    int c0 = tid * 8;
    float4 va[4][2];
#pragma unroll
    for (int r = 0; r < 4; r++) {
        const float* row = x + (size_t)(bg * 4 + r) * TOK * DIM + c0;
        va[r][0] = *(const float4*)row;
        va[r][1] = *(const float4*)(row + 4);
        float s  = va[r][0].x + va[r][0].y + va[r][0].z + va[r][0].w
                 + va[r][1].x + va[r][1].y + va[r][1].z + va[r][1].w;
        float ss = va[r][0].x * va[r][0].x + va[r][0].y * va[r][0].y
                 + va[r][0].z * va[r][0].z + va[r][0].w * va[r][0].w
                 + va[r][1].x * va[r][1].x + va[r][1].y * va[r][1].y
                 + va[r][1].z * va[r][1].z + va[r][1].w * va[r][1].w;
#pragma unroll
        for (int o = 16; o; o >>= 1) {
            s  += __shfl_xor_sync(0xffffffffu, s, o);
            ss += __shfl_xor_sync(0xffffffffu, ss, o);
        }
        if (lane == 0) { wred[r][wid][0] = s; wred[r][wid][1] = ss; }
    }
    __syncthreads();
    if (tid < 4) {
        float s  = wred[tid][0][0] + wred[tid][1][0] + wred[tid][2][0] + wred[tid][3][0];
        float ss = wred[tid][0][1] + wred[tid][1][1] + wred[tid][2][1] + wred[tid][3][1];
        float mu  = s * (1.0f / DIM);
        float var = ss * (1.0f / DIM) - mu * mu;
        stats[tid][0] = mu;
        stats[tid][1] = rsqrtf(var + 1e-5f);
    }
    __syncthreads();
    float4 gg0 = *(const float4*)(ln_g + c0), gg1 = *(const float4*)(ln_g + c0 + 4);
    float4 bb0 = *(const float4*)(ln_b + c0), bb1 = *(const float4*)(ln_b + c0 + 4);
#pragma unroll
    for (int r = 0; r < 4; r++) {
        float mu = stats[r][0], rs = stats[r][1];
        sh[r][c0 + 0] = (va[r][0].x - mu) * rs * gg0.x + bb0.x;
        sh[r][c0 + 1] = (va[r][0].y - mu) * rs * gg0.y + bb0.y;
        sh[r][c0 + 2] = (va[r][0].z - mu) * rs * gg0.z + bb0.z;
        sh[r][c0 + 3] = (va[r][0].w - mu) * rs * gg0.w + bb0.w;
        sh[r][c0 + 4] = (va[r][1].x - mu) * rs * gg1.x + bb1.x;
        sh[r][c0 + 5] = (va[r][1].y - mu) * rs * gg1.y + bb1.y;
        sh[r][c0 + 6] = (va[r][1].z - mu) * rs * gg1.z + bb1.z;
        sh[r][c0 + 7] = (va[r][1].w - mu) * rs * gg1.w + bb1.w;
    }
    __syncthreads();

    int jl = lane;
    int kc = wid;
    int j = j0 + jl;
    float a0 = 0.f, a1 = 0.f, a2 = 0.f, a3 = 0.f;
    const float* W = We1 + (size_t)(kc * 256) * DIM + j;
    const float* H0 = sh[0] + kc * 256;
    const float* H1 = sh[1] + kc * 256;
    const float* H2 = sh[2] + kc * 256;
    const float* H3 = sh[3] + kc * 256;
#pragma unroll 8
    for (int k = 0; k < 256; k++) {
        float w = W[(size_t)k * DIM];
        a0 = fmaf(H0[k], w, a0);
        a1 = fmaf(H1[k], w, a1);
        a2 = fmaf(H2[k], w, a2);
        a3 = fmaf(H3[k], w, a3);
    }
    red[0][tid] = a0; red[1][tid] = a1; red[2][tid] = a2; red[3][tid] = a3;
    __syncthreads();
    if (tid < 32) {
        float w2 = We2[j];
        float b1v = be1[j];
#pragma unroll
        for (int b = 0; b < 4; b++) {
            float s = red[b][jl] + red[b][jl + 32] + red[b][jl + 64] + red[b][jl + 96];
            float v = gelu_exact(s + b1v) * w2;
#pragma unroll
            for (int o = 16; o; o >>= 1) v += __shfl_xor_sync(0xffffffffu, v, o);
            if (jl == 0) atomicAdd(out + bg * 4 + b, v);
        }
    }
}

// ---------------------------------------------------------------------------
extern "C" void kernel_launch(void* const* d_in, const int* in_sizes, int n_in,
                              void* d_out, int out_size) {
    int o = (n_in == 16) ? 6 : 5;
    const float* x    = (const float*)d_in[0];
    const int*   ei   = (const int*)d_in[2];
    const float* dvec = (const float*)d_in[3];
    const float* dist = (const float*)d_in[4];
    const float* ln_g = (const float*)d_in[o + 0];
    const float* ln_b = (const float*)d_in[o + 1];
    const float* We1  = (const float*)d_in[o + 2];
    const float* be1  = (const float*)d_in[o + 3];
    const float* We2  = (const float*)d_in[o + 4];
    const float* be2  = (const float*)d_in[o + 5];
    const float* Wf1  = (const float*)d_in[o + 6];
    const float* bf1  = (const float*)d_in[o + 7];
    const float* Wf2  = (const float*)d_in[o + 8];
    const float* bf2  = (const float*)d_in[o + 9];
    float* out = (float*)d_out;

    static cudaStream_t s2 = nullptr;
    static cudaEvent_t evA, evW, evB, evE;
    if (!s2) {
        cudaStreamCreateWithFlags(&s2, cudaStreamNonBlocking);
        cudaEventCreateWithFlags(&evA, cudaEventDisableTiming);
        cudaEventCreateWithFlags(&evW, cudaEventDisableTiming);
        cudaEventCreateWithFlags(&evB, cudaEventDisableTiming);
        cudaEventCreateWithFlags(&evE, cudaEventDisableTiming);
        cudaFuncSetAttribute(k_gemm_mma, cudaFuncAttributeMaxDynamicSharedMemorySize,
                             GEMM_SMEM);
    }

    // Fork: s2 runs cvt_w (parallel with cvt_a) then energy (parallel with gemm).
    cudaEventRecord(evA, 0);
    cudaStreamWaitEvent(s2, evA, 0);
    k_cvt_w<<<dim3(64, 16), dim3(32, 32), 0, s2>>>(Wf1);
    cudaEventRecord(evW, s2);

    k_cvt_a<<<NNODES * DIM / 4 / 256, 256>>>(x, out, be2);   // legacy stream
    cudaEventRecord(evB, 0);

    cudaStreamWaitEvent(s2, evB, 0);                          // energy needs out init
    k_energy<<<dim3(32, 8), 128, 0, s2>>>(x, ln_g, ln_b, We1, be1, We2, out);
    cudaEventRecord(evE, s2);

    cudaStreamWaitEvent(0, evW, 0);                           // gemm needs cvt_w
    k_gemm_mma<<<dim3(16, 16), 256, GEMM_SMEM>>>(bf1);
    k_edge<<<NEDGE / (8 * EPW), 256>>>(ei, dvec, dist, Wf2, bf2, out);
    cudaStreamWaitEvent(0, evE, 0);                           // join before harness reads
}